// round 5
// baseline (speedup 1.0000x reference)
#include <cuda_runtime.h>
#include <cuda_bf16.h>

// TD(lambda) backward scan — block-per-row affine suffix scan.
//
// ret_t = a_t * ret_{t+1} + b_t,  a_t = gamma*(1-d_t)*lam_t,
//                                 b_t = r_t + gamma*(1-d_t)*(1-lam_t)*v_{t+1}
// ret_t = (a_t o a_{t+1} o ... o a_{S-1})(v_init),  v_init = values[b,S].
//
// One block of 512 threads per row, one timestep per thread:
//   - fully coalesced direct LDG of r, d, v_next (no smem staging/transpose)
//   - warp-level suffix scan of affine pairs via shfl (5 rounds)
//   - cross-warp suffix scan of 16 warp totals (warp 0, smem)
//   - apply to v_init, directly coalesced STG of ret.

#define B_TOT 32768
#define S_LEN 512
#define EPS_F 1e-8f

__global__ __launch_bounds__(S_LEN)
void gamma_lambda_scan2_kernel(
    const float* __restrict__ values,    // [B, S+1]
    const float* __restrict__ rewards,   // [B, S]
    const float* __restrict__ dones,     // [B, S]
    const float* __restrict__ raw_gamma, // [1]
    const float* __restrict__ raw_lambd, // [S]
    float* __restrict__ out)             // [B, S]
{
    __shared__ float sA[16];
    __shared__ float sB[16];
    __shared__ float s_vinit;

    const int t    = threadIdx.x;        // timestep 0..511
    const int lane = t & 31;
    const int wid  = t >> 5;             // 0..15
    const int row  = blockIdx.x;

    const float* vrow = values  + (size_t)row * (S_LEN + 1);
    const float* rrow = rewards + (size_t)row * S_LEN;
    const float* drow = dones   + (size_t)row * S_LEN;

    // ---- coalesced loads + per-element affine map ----
    const float gamma = fmaxf(tanhf(__ldg(raw_gamma)), EPS_F);
    const float lam   = fmaxf(tanhf(__ldg(raw_lambd + t)), EPS_F);
    const float r  = rrow[t];
    const float d  = drow[t];
    const float vn = vrow[t + 1];        // v_next; t==511 -> values[S] = v_init

    if (t == S_LEN - 1) s_vinit = vn;

    const float gd = gamma - gamma * d;          // gamma*(1-d)
    float A = gd * lam;                          // a_t
    float Bc = fmaf(gd - A, vn, r);              // b_t = r + gd*(1-lam)*v

    // keep own map for the final application
    const float A_self = A, B_self = Bc;
    (void)A_self; (void)B_self;

    // ---- warp suffix-inclusive scan: lane l -> compose of [l .. 31] ----
    // compose P o Q (Q applied first): A = A_P*A_Q, B = fma(A_P, B_Q, B_P)
#pragma unroll
    for (int off = 1; off < 32; off <<= 1) {
        const float A2 = __shfl_down_sync(0xFFFFFFFFu, A,  off);
        const float B2 = __shfl_down_sync(0xFFFFFFFFu, Bc, off);
        if (lane + off < 32) {
            Bc = fmaf(A, B2, Bc);
            A  = A * A2;
        }
    }

    // lane 0 holds full-warp composition -> publish warp totals
    if (lane == 0) { sA[wid] = A; sB[wid] = Bc; }
    __syncthreads();

    // ---- warp 0: suffix scan of 16 warp totals -> exclusive suffixes ----
    if (wid == 0) {
        float Aw = 1.0f, Bw = 0.0f;
        if (lane < 16) { Aw = sA[lane]; Bw = sB[lane]; }
#pragma unroll
        for (int off = 1; off < 16; off <<= 1) {
            const float A2 = __shfl_down_sync(0xFFFFFFFFu, Aw, off);
            const float B2 = __shfl_down_sync(0xFFFFFFFFu, Bw, off);
            if (lane + off < 16) {
                Bw = fmaf(Aw, B2, Bw);
                Aw = Aw * A2;
            }
        }
        // exclusive: warp w needs suffix of warps w+1..15 (identity for w=15)
        float Ae = __shfl_down_sync(0xFFFFFFFFu, Aw, 1);
        float Be = __shfl_down_sync(0xFFFFFFFFu, Bw, 1);
        if (lane == 15) { Ae = 1.0f; Be = 0.0f; }
        if (lane < 16) { sA[lane] = Ae; sB[lane] = Be; }
    }
    __syncthreads();

    // ---- apply: ret_t = S_t( E_wid( v_init ) ) ----
    const float v_init = s_vinit;
    const float x1  = fmaf(sA[wid], v_init, sB[wid]);   // smem broadcast
    const float ret = fmaf(A, x1, Bc);

    out[(size_t)row * S_LEN + t] = ret;                 // coalesced
}

extern "C" void kernel_launch(void* const* d_in, const int* in_sizes, int n_in,
                              void* d_out, int out_size)
{
    const float* values    = (const float*)d_in[0];
    const float* rewards   = (const float*)d_in[1];
    const float* dones     = (const float*)d_in[2];
    const float* raw_gamma = (const float*)d_in[3];
    const float* raw_lambd = (const float*)d_in[4];
    float* out = (float*)d_out;

    gamma_lambda_scan2_kernel<<<B_TOT, S_LEN>>>(values, rewards, dones,
                                                raw_gamma, raw_lambd, out);
}

// round 6
// speedup vs baseline: 1.9404x; 1.9404x over previous
#include <cuda_runtime.h>
#include <cuda_bf16.h>

// TD(lambda) backward scan — warp-per-row, 4-elem micro-segments + warp scan.
//
// ret_t = a_t*ret_{t+1} + b_t;  a_t = gamma*(1-d_t)*lam_t,
//                               b_t = r_t + gamma*(1-d_t)*(1-lam_t)*v_{t+1}
// Lane l, chunk c owns elements [128c+4l, 128c+4l+4): serial compose of the
// 4-elem segment -> per-chunk warp suffix scan (shfl, 4 independent scans) ->
// serial compose of 4 chunk totals -> replay. r/d/out are aligned coalesced
// float4; v_next staged shifted through a small per-warp smem slab so its
// odd row stride (513) never breaks alignment.

#define B_TOT 32768
#define S_LEN 512
#define EPS_F 1e-8f

static constexpr int WPB = 8;   // warps (rows) per block -> 256 threads

__global__ __launch_bounds__(WPB * 32)
void gamma_lambda_wscan_kernel(
    const float* __restrict__ values,    // [B, S+1]
    const float* __restrict__ rewards,   // [B, S]
    const float* __restrict__ dones,     // [B, S]
    const float* __restrict__ raw_gamma, // [1]
    const float* __restrict__ raw_lambd, // [S]
    float* __restrict__ out)             // [B, S]
{
    __shared__ __align__(16) float s_lam[S_LEN];
    __shared__ __align__(16) float s_v[WPB][S_LEN];  // v_next per warp (shifted)
    __shared__ float s_gamma;

    const int tid  = threadIdx.x;
    const int lane = tid & 31;
    const int wid  = tid >> 5;

    for (int i = tid; i < S_LEN; i += WPB * 32)
        s_lam[i] = fmaxf(tanhf(raw_lambd[i]), EPS_F);
    if (tid == 0) s_gamma = fmaxf(tanhf(raw_gamma[0]), EPS_F);

    const int row = blockIdx.x * WPB + wid;          // exact: 4096*8 = 32768
    const float* vrow = values  + (size_t)row * (S_LEN + 1);
    const float* rrow = rewards + (size_t)row * S_LEN;
    const float* drow = dones   + (size_t)row * S_LEN;
    float*       orow = out     + (size_t)row * S_LEN;

    // Stage v_next shifted: s_v[i] = values[row, i+1]. Coalesced scalar LDG.
    float* __restrict__ wv = s_v[wid];
#pragma unroll
    for (int k = 0; k < 16; k++)
        wv[k * 32 + lane] = vrow[1 + k * 32 + lane];
    __syncthreads();   // covers s_lam, s_gamma, and s_v

    const float gamma = s_gamma;

    // ---- per-chunk: aligned coalesced loads, build (a,b), compose segment ----
    float a[4][4], b[4][4];
    float A[4], Bv[4];
#pragma unroll
    for (int c = 0; c < 4; c++) {
        const int base = c * 128 + lane * 4;
        const float4 r4 = *(const float4*)(rrow  + base);
        const float4 d4 = *(const float4*)(drow  + base);
        const float4 v4 = *(const float4*)(wv    + base);   // LDS.128, conflict-free
        const float4 l4 = *(const float4*)(s_lam + base);
        const float rr[4] = {r4.x, r4.y, r4.z, r4.w};
        const float dd[4] = {d4.x, d4.y, d4.z, d4.w};
        const float vv[4] = {v4.x, v4.y, v4.z, v4.w};
        const float ll[4] = {l4.x, l4.y, l4.z, l4.w};
        float Ac = 1.0f, Bc = 0.0f;
#pragma unroll
        for (int j = 3; j >= 0; --j) {
            const float gd = gamma - gamma * dd[j];          // gamma*(1-d)
            const float aj = gd * ll[j];
            const float bj = fmaf(gd - aj, vv[j], rr[j]);    // r + gd*(1-lam)*v
            a[c][j] = aj; b[c][j] = bj;
            Bc = fmaf(aj, Bc, bj);                           // compose backward
            Ac = aj * Ac;
        }
        A[c] = Ac; Bv[c] = Bc;
    }

    // ---- 4 independent warp suffix-inclusive scans (lanes l..31) ----
#pragma unroll
    for (int off = 1; off < 32; off <<= 1) {
#pragma unroll
        for (int c = 0; c < 4; c++) {
            const float A2 = __shfl_down_sync(0xFFFFFFFFu, A[c],  off);
            const float B2 = __shfl_down_sync(0xFFFFFFFFu, Bv[c], off);
            if (lane + off < 32) {
                Bv[c] = fmaf(A[c], B2, Bv[c]);
                A[c]  = A[c] * A2;
            }
        }
    }

    // chunk totals (lane 0 holds full-chunk map), broadcast to all lanes
    float TA[4], TB[4];
#pragma unroll
    for (int c = 0; c < 4; c++) {
        TA[c] = __shfl_sync(0xFFFFFFFFu, A[c],  0);
        TB[c] = __shfl_sync(0xFFFFFFFFu, Bv[c], 0);
    }

    // exclusive per-lane suffix within each chunk (lanes l+1..31)
    float Ae[4], Be[4];
#pragma unroll
    for (int c = 0; c < 4; c++) {
        Ae[c] = __shfl_down_sync(0xFFFFFFFFu, A[c],  1);
        Be[c] = __shfl_down_sync(0xFFFFFFFFu, Bv[c], 1);
        if (lane == 31) { Ae[c] = 1.0f; Be[c] = 0.0f; }
    }

    // ---- chunk boundary values: x[c] = ret_{128(c+1)}; x[3] = values[b,S] ----
    const float v_init = wv[S_LEN - 1];   // = values[row, 512], warp broadcast
    float x[4];
    x[3] = v_init;
    x[2] = fmaf(TA[3], x[3], TB[3]);      // ret_384
    x[1] = fmaf(TA[2], x[2], TB[2]);      // ret_256
    x[0] = fmaf(TA[1], x[1], TB[1]);      // ret_128

    // ---- replay 4-elem segments, aligned coalesced float4 stores ----
#pragma unroll
    for (int c = 0; c < 4; c++) {
        const float y  = fmaf(Ae[c], x[c], Be[c]);   // ret at my segment's right edge
        const float o3 = fmaf(a[c][3], y,  b[c][3]);
        const float o2 = fmaf(a[c][2], o3, b[c][2]);
        const float o1 = fmaf(a[c][1], o2, b[c][1]);
        const float o0 = fmaf(a[c][0], o1, b[c][0]);
        *(float4*)(orow + c * 128 + lane * 4) = make_float4(o0, o1, o2, o3);
    }
}

extern "C" void kernel_launch(void* const* d_in, const int* in_sizes, int n_in,
                              void* d_out, int out_size)
{
    const float* values    = (const float*)d_in[0];
    const float* rewards   = (const float*)d_in[1];
    const float* dones     = (const float*)d_in[2];
    const float* raw_gamma = (const float*)d_in[3];
    const float* raw_lambd = (const float*)d_in[4];
    float* out = (float*)d_out;

    const int threads = WPB * 32;          // 256
    const int blocks  = B_TOT / WPB;       // 4096
    gamma_lambda_wscan_kernel<<<blocks, threads>>>(values, rewards, dones,
                                                   raw_gamma, raw_lambd, out);
}